// round 4
// baseline (speedup 1.0000x reference)
#include <cuda_runtime.h>
#include <cuda_bf16.h>

// RippleNet: predicts[b] = sigmoid( sum_d user_rep[b][d] * item_e[b][d] )
//   user_rep = sum_h sum_m softmax_m( (R[r_hbm] @ head_hbm) . item_b ) * tail_hbm
// Restructure: (R h).item == (R^T item).h  -> precompute q[r] = R^T item per b
// (only 32 relations), turning each memory's 16x16 matvec into a 16-dot.
//
// H=2, B=2048, M=64, D=16, N_ENT=500000, N_REL=32.
// ent_emb (32MB) fits in L2 -> gathers are L2 hits in steady state.

#define NUM_H   2
#define NUM_B   2048
#define NUM_M   64
#define DIM     16
#define NUM_REL 32
#define B_PER_BLK 4
#define THREADS  256   // 8 warps: 4 b's x 2 hops

__global__ __launch_bounds__(THREADS, 6)
void ripplenet_kernel(const int*   __restrict__ items,
                      const int*   __restrict__ heads,
                      const int*   __restrict__ rels,
                      const int*   __restrict__ tails,
                      const float* __restrict__ ent,
                      const float* __restrict__ rel,
                      float*       __restrict__ out)
{
    __shared__ float q_sh[B_PER_BLK][NUM_REL][DIM];   // 8 KB: q[r] = R[r]^T item
    __shared__ float item_sh[B_PER_BLK][DIM];
    __shared__ float prob_sh[THREADS/32][NUM_M];      // logits -> probs, per warp
    __shared__ float user_sh[B_PER_BLK][2][DIM];

    const int tid  = threadIdx.x;
    const int warp = tid >> 5;
    const int lane = tid & 31;
    const int bl   = warp >> 1;      // local batch index 0..3
    const int hop  = warp & 1;       // which hop this warp handles
    const int b    = blockIdx.x * B_PER_BLK + bl;
    const int grp  = lane >> 4;      // half-warp id (0/1): memory m parity
    const int li   = lane & 15;      // dim index within half-warp

    // ---- item embedding -> shared (16 lanes of hop-0 warp per b) ----
    if (hop == 0 && lane < DIM)
        item_sh[bl][lane] = ent[items[b] * DIM + lane];
    __syncthreads();

    // ---- precompute q[r][i] = sum_j rel[r][j][i] * item[j]  (64 thr per b) ----
    {
        const int p  = hop * 32 + lane;   // 0..63
        const int i  = p & 15;
        const int r0 = p >> 4;            // 0..3
        #pragma unroll
        for (int k = 0; k < 8; ++k) {
            const int r = r0 + 4 * k;
            const float* Rr = rel + r * DIM * DIM;
            float acc = 0.f;
            #pragma unroll
            for (int j = 0; j < DIM; ++j)
                acc = fmaf(Rr[j * DIM + i], item_sh[bl][j], acc);  // coalesced, L1-resident
            q_sh[bl][r][i] = acc;
        }
    }
    __syncthreads();

    // ---- per-(hop,b) index preload: all 64 m's worth, 2 regs each ----
    const int base  = (hop * NUM_B + b) * NUM_M;
    const int hidx0 = heads[base + lane], hidx1 = heads[base + 32 + lane];
    const int ridx0 = rels [base + lane], ridx1 = rels [base + 32 + lane];
    const int tidx0 = tails[base + lane], tidx1 = tails[base + 32 + lane];

    // ---- logit pass: half-warp per memory, 2 memories/iter ----
    #pragma unroll 4
    for (int t = 0; t < 32; ++t) {
        const int m   = 2 * t + grp;          // t<16 -> m<32 (uniform across warp)
        const int src = m & 31;
        const int hidx = __shfl_sync(0xffffffffu, (t < 16) ? hidx0 : hidx1, src);
        const int ridx = __shfl_sync(0xffffffffu, (t < 16) ? ridx0 : ridx1, src);
        // coalesced 64B gather per half-warp; q from shared (conflict-free in half)
        float partial = q_sh[bl][ridx][li] * ent[hidx * DIM + li];
        #pragma unroll
        for (int o = 8; o >= 1; o >>= 1)
            partial += __shfl_xor_sync(0xffffffffu, partial, o, 16);
        if (li == 0) prob_sh[warp][m] = partial;
    }
    __syncwarp();

    // ---- softmax over M=64 (each lane owns 2 logits) ----
    const float l0 = prob_sh[warp][lane];
    const float l1 = prob_sh[warp][lane + 32];
    float mx = fmaxf(l0, l1);
    #pragma unroll
    for (int o = 16; o >= 1; o >>= 1)
        mx = fmaxf(mx, __shfl_xor_sync(0xffffffffu, mx, o));
    const float e0 = __expf(l0 - mx), e1 = __expf(l1 - mx);
    float s = e0 + e1;
    #pragma unroll
    for (int o = 16; o >= 1; o >>= 1)
        s += __shfl_xor_sync(0xffffffffu, s, o);
    const float inv = __frcp_rn(s);
    prob_sh[warp][lane]      = e0 * inv;
    prob_sh[warp][lane + 32] = e1 * inv;
    __syncwarp();

    // ---- weighted tail aggregation: user_rep contribution of this hop ----
    float acc = 0.f;
    #pragma unroll 8
    for (int t = 0; t < 32; ++t) {
        const int m = 2 * t + grp;
        const int tidx = __shfl_sync(0xffffffffu, (t < 16) ? tidx0 : tidx1, m & 31);
        acc = fmaf(prob_sh[warp][m], ent[tidx * DIM + li], acc);
    }
    acc += __shfl_xor_sync(0xffffffffu, acc, 16);   // combine the two m-streams
    if (lane < DIM) user_sh[bl][hop][lane] = acc;
    __syncthreads();

    // ---- combine hops, dot with item, sigmoid ----
    if (hop == 0) {
        const float ur = user_sh[bl][0][li] + user_sh[bl][1][li];
        float d = ur * item_sh[bl][li];
        #pragma unroll
        for (int o = 8; o >= 1; o >>= 1)
            d += __shfl_xor_sync(0xffffffffu, d, o, 16);
        if (lane == 0) out[b] = __frcp_rn(1.f + __expf(-d));
    }
}

extern "C" void kernel_launch(void* const* d_in, const int* in_sizes, int n_in,
                              void* d_out, int out_size)
{
    const int*   items = (const int*)  d_in[0];
    const int*   heads = (const int*)  d_in[1];
    const int*   rels  = (const int*)  d_in[2];
    const int*   tails = (const int*)  d_in[3];
    const float* ent   = (const float*)d_in[4];
    const float* rel   = (const float*)d_in[5];
    float*       out   = (float*)d_out;

    ripplenet_kernel<<<NUM_B / B_PER_BLK, THREADS>>>(
        items, heads, rels, tails, ent, rel, out);
}